// round 7
// baseline (speedup 1.0000x reference)
#include <cuda_runtime.h>
#include <cuda_bf16.h>
#include <cuda_fp16.h>

#define N_NODES 40000
#define N_EDGES 640000
#define EMBED   128
#define NTYPE   64

// ---------------- scratch (static device globals; no allocs allowed) ----------------
__device__ __half         g_t[N_NODES * EMBED];    // post-GEMM features, fp16
__device__ unsigned short g_hb[N_NODES * EMBED];   // bf16 bits, high part
__device__ unsigned short g_hl[N_NODES * EMBED];   // bf16 bits, low part
__device__ int   g_counts[N_NODES];
__device__ int   g_rowptr[N_NODES + 1];
__device__ int   g_cursor[N_NODES];
__device__ float g_dinv[N_NODES];
__device__ float g_selfw[N_NODES];
__device__ int2  g_edges[N_EDGES];
__device__ int   g_x64;
__device__ int   g_e64;
// weights as bf16 hi/lo, layout [n][k] (k contiguous)
__device__ unsigned short g_Wch[128 * 128];
__device__ unsigned short g_Wcl[128 * 128];
__device__ unsigned short g_Wdh[64 * 128];
__device__ unsigned short g_Wdl[64 * 128];

// ---------------- helpers ----------------
__device__ __forceinline__ int load_idx(const void* p, long long i, int is64) {
    if (is64) return (int)((const long long*)p)[i];
    return ((const int*)p)[i];
}

__device__ __forceinline__ unsigned short f2bf(float x) {
    return __bfloat16_as_ushort(__float2bfloat16_rn(x));
}
__device__ __forceinline__ float bf2f(unsigned short u) {
    return __bfloat162float(__ushort_as_bfloat16(u));
}

__device__ __forceinline__ unsigned int smem_u32(const void* p) {
    unsigned int a;
    asm("{ .reg .u64 t; cvta.to.shared.u64 t, %1; cvt.u32.u64 %0, t; }" : "=r"(a) : "l"(p));
    return a;
}

__device__ __forceinline__ int2 shfl_e(int2 v, int src) {
    int2 r;
    r.x = __shfl_sync(0xffffffffu, v.x, src);
    r.y = __shfl_sync(0xffffffffu, v.y, src);
    return r;
}

__device__ __forceinline__ void ldsm_x4(unsigned int& r0, unsigned int& r1,
                                        unsigned int& r2, unsigned int& r3,
                                        unsigned int addr) {
    asm volatile("ldmatrix.sync.aligned.m8n8.x4.shared.b16 {%0,%1,%2,%3}, [%4];"
                 : "=r"(r0), "=r"(r1), "=r"(r2), "=r"(r3) : "r"(addr));
}

__device__ __forceinline__ void ldsm_x2(unsigned int& r0, unsigned int& r1,
                                        unsigned int addr) {
    asm volatile("ldmatrix.sync.aligned.m8n8.x2.shared.b16 {%0,%1}, [%2];"
                 : "=r"(r0), "=r"(r1) : "r"(addr));
}

__device__ __forceinline__ void mma_bf16(float* d, unsigned int a0, unsigned int a1,
                                         unsigned int a2, unsigned int a3,
                                         unsigned int b0, unsigned int b1) {
    asm volatile(
        "mma.sync.aligned.m16n8k16.row.col.f32.bf16.bf16.f32 "
        "{%0,%1,%2,%3}, {%4,%5,%6,%7}, {%8,%9}, {%0,%1,%2,%3};"
        : "+f"(d[0]), "+f"(d[1]), "+f"(d[2]), "+f"(d[3])
        : "r"(a0), "r"(a1), "r"(a2), "r"(a3), "r"(b0), "r"(b1));
}

// ---------------- init: dtype detect (thread 0) + zero counts ----------------
__global__ void k_init(const void* xp, const void* ep) {
    int i = blockIdx.x * blockDim.x + threadIdx.x;
    if (i < N_NODES) g_counts[i] = 0;
    if (i == 0) {
        const unsigned int* w = (const unsigned int*)xp;
        int is64 = 1;
        for (int q = 0; q < 64; q++) {
            if (w[2 * q + 1] != 0u) { is64 = 0; break; }
        }
        g_x64 = is64;
        const unsigned int* we = (const unsigned int*)ep;
        int e64 = 1;
        for (int q = 0; q < 64; q++) {
            if (we[2 * q + 1] != 0u) { e64 = 0; break; }
        }
        g_e64 = e64;
    }
}

__global__ void k_count(const void* ei) {
    int e = blockIdx.x * blockDim.x + threadIdx.x;
    if (e < N_EDGES) {
        int d = load_idx(ei, (long long)N_EDGES + e, g_e64);
        atomicAdd(&g_counts[d], 1);
    }
}

// scan + dinv in one single-block kernel
__global__ void k_scan_dinv() {
    __shared__ int partial[1024];
    const int CH = (N_NODES + 1023) / 1024;   // 40
    int t = threadIdx.x;
    int base = t * CH;
    int cnt[CH];
    int s = 0;
    for (int i = 0; i < CH; i++) {
        int idx = base + i;
        int c = (idx < N_NODES) ? g_counts[idx] : 0;
        cnt[i] = c;
        s += c;
    }
    partial[t] = s;
    __syncthreads();
    for (int off = 1; off < 1024; off <<= 1) {
        int xv = (t >= off) ? partial[t - off] : 0;
        __syncthreads();
        partial[t] += xv;
        __syncthreads();
    }
    int run = partial[t] - s;
    for (int i = 0; i < CH; i++) {
        int idx = base + i;
        if (idx < N_NODES) {
            g_rowptr[idx] = run;
            g_cursor[idx] = run;
            run += cnt[i];
            float dv = rsqrtf((float)(cnt[i] + 1));
            g_dinv[idx] = dv;
            g_selfw[idx] = dv * dv;
        }
    }
    if (t == 1023) g_rowptr[N_NODES] = run;
}

__global__ void k_fill(const void* ei) {
    int e = blockIdx.x * blockDim.x + threadIdx.x;
    if (e < N_EDGES) {
        int is64 = g_e64;
        int s = load_idx(ei, e, is64);
        int d = load_idx(ei, (long long)N_EDGES + e, is64);
        int pos = atomicAdd(&g_cursor[d], 1);
        int2 v;
        v.x = s;
        v.y = __float_as_int(g_dinv[s] * g_dinv[d]);
        g_edges[pos] = v;
    }
}

// ---------------- fused weight-prep + embedding gather ----------------
__global__ void k_prep_embed(const float* __restrict__ Wc, const float* __restrict__ Wd,
                             const void* xp, const float* __restrict__ Win) {
    if (blockIdx.x < 96) {
        int i = blockIdx.x * 256 + threadIdx.x;
        if (i < 16384) {
            int n = i >> 7;
            int k = i & 127;
            float v = Wc[k * 128 + n];
            unsigned short h = f2bf(v);
            unsigned short l = f2bf(v - bf2f(h));
            g_Wch[n * 128 + k] = h;
            g_Wcl[n * 128 + k] = l;
        } else {
            int j = i - 16384;
            int n = j >> 7;
            int k = j & 127;
            float v = Wd[k * 64 + n];
            unsigned short h = f2bf(v);
            unsigned short l = f2bf(v - bf2f(h));
            g_Wdh[n * 128 + k] = h;
            g_Wdl[n * 128 + k] = l;
        }
    } else {
        int id = (blockIdx.x - 96) * 256 + threadIdx.x;
        if (id < N_NODES * 16) {
            int v = id >> 4;
            int k0 = (id & 15) * 8;
            int row = load_idx(xp, v, g_x64);
            const float* src = Win + (long)row * EMBED + k0;
            unsigned short hb[8];
            unsigned short lb[8];
            #pragma unroll
            for (int q = 0; q < 8; q++) {
                float a = src[q];
                unsigned short h = f2bf(a);
                hb[q] = h;
                lb[q] = f2bf(a - bf2f(h));
            }
            *(uint4*)(g_hb + (long)v * EMBED + k0) = *(uint4*)hb;
            *(uint4*)(g_hl + (long)v * EMBED + k0) = *(uint4*)lb;
        }
    }
}

// ---------------- tensor-core GEMM (mma.sync bf16, split hi/lo) ----------
template <int NCOL>
__device__ __forceinline__ void mma_gemm_body(const unsigned short* __restrict__ Wh,
                                              const unsigned short* __restrict__ Wl,
                                              __half* __restrict__ C) {
    const int PAD = 136;
    const int NT = NCOL / 8;
    extern __shared__ unsigned short sm[];
    unsigned short* Ah = sm;                       // [128][PAD]
    unsigned short* Al = Ah + 128 * PAD;
    unsigned short* Bs = Al + 128 * PAD;           // [NCOL][PAD], Bh then Bl

    int tid = threadIdx.x;
    int wid = tid >> 5;
    int lane = tid & 31;
    int row0 = blockIdx.x * 128;

    for (int i = tid; i < 2048; i += 256) {
        int r = i >> 4;
        int k0 = (i & 15) * 8;
        int gr = row0 + r;
        uint4 vh = make_uint4(0u, 0u, 0u, 0u);
        uint4 vl = make_uint4(0u, 0u, 0u, 0u);
        if (gr < N_NODES) {
            vh = *(const uint4*)(g_hb + (long)gr * EMBED + k0);
            vl = *(const uint4*)(g_hl + (long)gr * EMBED + k0);
        }
        *(uint4*)(Ah + r * PAD + k0) = vh;
        *(uint4*)(Al + r * PAD + k0) = vl;
    }
    for (int i = tid; i < NCOL * 16; i += 256) {
        int r = i >> 4;
        int k0 = (i & 15) * 8;
        *(uint4*)(Bs + r * PAD + k0) = *(const uint4*)(Wh + r * 128 + k0);
    }
    __syncthreads();

    int m0 = wid * 16;
    float acc[NT][4];
    #pragma unroll
    for (int j = 0; j < NT; j++) {
        #pragma unroll
        for (int q = 0; q < 4; q++) acc[j][q] = 0.0f;
    }

    const unsigned int sb = smem_u32(sm);
    unsigned int a_off = (unsigned int)((m0 + (lane & 15)) * PAD + (lane >> 4) * 8) * 2u;
    unsigned int b_off = (unsigned int)(((lane & 15) & 7) * PAD + ((lane & 15) >> 3) * 8) * 2u;
    unsigned int a_h = sb + a_off;
    unsigned int a_l = a_h + (unsigned int)(128 * PAD * 2);
    unsigned int b_b = sb + (unsigned int)(256 * PAD * 2) + b_off;

    // fused passes: (Ah + Al) against Bh, sharing each B fragment
    #pragma unroll
    for (int ks = 0; ks < 8; ks++) {
        unsigned int h0, h1, h2, h3;
        unsigned int l0, l1, l2, l3;
        ldsm_x4(h0, h1, h2, h3, a_h + (unsigned int)(ks * 32));
        ldsm_x4(l0, l1, l2, l3, a_l + (unsigned int)(ks * 32));
        #pragma unroll
        for (int j = 0; j < NT; j++) {
            unsigned int b0, b1;
            ldsm_x2(b0, b1, b_b + (unsigned int)(j * 8 * PAD * 2 + ks * 32));
            mma_bf16(acc[j], h0, h1, h2, h3, b0, b1);
            mma_bf16(acc[j], l0, l1, l2, l3, b0, b1);
        }
    }
    // restage B with Wl
    __syncthreads();
    for (int i = tid; i < NCOL * 16; i += 256) {
        int r = i >> 4;
        int k0 = (i & 15) * 8;
        *(uint4*)(Bs + r * PAD + k0) = *(const uint4*)(Wl + r * 128 + k0);
    }
    __syncthreads();
    // pass 2: Ah*Bl
    #pragma unroll
    for (int ks = 0; ks < 8; ks++) {
        unsigned int h0, h1, h2, h3;
        ldsm_x4(h0, h1, h2, h3, a_h + (unsigned int)(ks * 32));
        #pragma unroll
        for (int j = 0; j < NT; j++) {
            unsigned int b0, b1;
            ldsm_x2(b0, b1, b_b + (unsigned int)(j * 8 * PAD * 2 + ks * 32));
            mma_bf16(acc[j], h0, h1, h2, h3, b0, b1);
        }
    }

    // epilogue: fp16 stores
    int mrow = m0 + (lane >> 2);
    int nc0 = (lane & 3) * 2;
    int gr0 = row0 + mrow;
    int gr1 = gr0 + 8;
    #pragma unroll
    for (int j = 0; j < NT; j++) {
        if (gr0 < N_NODES) {
            *(__half2*)(C + (long)gr0 * NCOL + j * 8 + nc0) =
                __floats2half2_rn(acc[j][0], acc[j][1]);
        }
        if (gr1 < N_NODES) {
            *(__half2*)(C + (long)gr1 * NCOL + j * 8 + nc0) =
                __floats2half2_rn(acc[j][2], acc[j][3]);
        }
    }
}

__global__ void __launch_bounds__(256, 2) k_mm_conv() {
    mma_gemm_body<128>(g_Wch, g_Wcl, g_t);
}
__global__ void __launch_bounds__(256, 2) k_mm_dec() {
    mma_gemm_body<64>(g_Wdh, g_Wdl, g_t);
}

// ---------------- aggregation: register-staged edges + shfl broadcast ----------------
// Lanes hold edges jb+lane and jb+32+lane; inner loop shfl-broadcasts them, so
// the only memory latency in the loop is the row gather itself.
__global__ void __launch_bounds__(256) k_agg_conv(const float* __restrict__ bias) {
    const __half* T = g_t;
    int v = blockIdx.x * 8 + (threadIdx.x >> 5);
    int lane = threadIdx.x & 31;
    int lo4 = lane * 4;

    float acc[4];
    float sw = g_selfw[v];
    {
        uint2 raw = *(const uint2*)(T + (long)v * 128 + lo4);
        float2 p0 = __half22float2(*(__half2*)&raw.x);
        float2 p1 = __half22float2(*(__half2*)&raw.y);
        acc[0] = sw * p0.x; acc[1] = sw * p0.y;
        acc[2] = sw * p1.x; acc[3] = sw * p1.y;
    }

    int jb = g_rowptr[v];
    int je = g_rowptr[v + 1];
    int cnt = je - jb;

    int2 myE0 = make_int2(0, 0);
    int2 myE1 = make_int2(0, 0);
    if (lane < cnt) myE0 = g_edges[jb + lane];
    if (32 + lane < cnt) myE1 = g_edges[jb + 32 + lane];

    int rc = (cnt < 64) ? cnt : 64;
    int j = 0;
    for (; j + 1 < rc; j += 2) {
        int2 ea = (j < 32) ? shfl_e(myE0, j) : shfl_e(myE1, j - 32);
        int j1 = j + 1;
        int2 eb = (j1 < 32) ? shfl_e(myE0, j1) : shfl_e(myE1, j1 - 32);
        uint2 r0 = *(const uint2*)(T + (long)ea.x * 128 + lo4);
        uint2 r1 = *(const uint2*)(T + (long)eb.x * 128 + lo4);
        float w0 = __int_as_float(ea.y);
        float w1 = __int_as_float(eb.y);
        float2 a0 = __half22float2(*(__half2*)&r0.x);
        float2 a1 = __half22float2(*(__half2*)&r0.y);
        float2 b0 = __half22float2(*(__half2*)&r1.x);
        float2 b1 = __half22float2(*(__half2*)&r1.y);
        acc[0] = fmaf(w0, a0.x, acc[0]); acc[1] = fmaf(w0, a0.y, acc[1]);
        acc[2] = fmaf(w0, a1.x, acc[2]); acc[3] = fmaf(w0, a1.y, acc[3]);
        acc[0] = fmaf(w1, b0.x, acc[0]); acc[1] = fmaf(w1, b0.y, acc[1]);
        acc[2] = fmaf(w1, b1.x, acc[2]); acc[3] = fmaf(w1, b1.y, acc[3]);
    }
    if (j < rc) {
        int2 ea = (j < 32) ? shfl_e(myE0, j) : shfl_e(myE1, j - 32);
        uint2 r0 = *(const uint2*)(T + (long)ea.x * 128 + lo4);
        float w0 = __int_as_float(ea.y);
        float2 a0 = __half22float2(*(__half2*)&r0.x);
        float2 a1 = __half22float2(*(__half2*)&r0.y);
        acc[0] = fmaf(w0, a0.x, acc[0]); acc[1] = fmaf(w0, a0.y, acc[1]);
        acc[2] = fmaf(w0, a1.x, acc[2]); acc[3] = fmaf(w0, a1.y, acc[3]);
    }
    // rare fallback: degree > 64
    for (int q = 64; q < cnt; q++) {
        int2 e0 = g_edges[jb + q];
        uint2 r0 = *(const uint2*)(T + (long)e0.x * 128 + lo4);
        float w0 = __int_as_float(e0.y);
        float2 a0 = __half22float2(*(__half2*)&r0.x);
        float2 a1 = __half22float2(*(__half2*)&r0.y);
        acc[0] = fmaf(w0, a0.x, acc[0]); acc[1] = fmaf(w0, a0.y, acc[1]);
        acc[2] = fmaf(w0, a1.x, acc[2]); acc[3] = fmaf(w0, a1.y, acc[3]);
    }

    unsigned short hb[4];
    unsigned short lb[4];
    #pragma unroll
    for (int i = 0; i < 4; i++) {
        float a = fmaxf(acc[i] + bias[lo4 + i], 0.0f);
        unsigned short h = f2bf(a);
        hb[i] = h;
        lb[i] = f2bf(a - bf2f(h));
    }
    *(uint2*)(g_hb + (long)v * 128 + lo4) = *(uint2*)hb;
    *(uint2*)(g_hl + (long)v * 128 + lo4) = *(uint2*)lb;
}

__global__ void __launch_bounds__(256) k_agg_dec(const float* __restrict__ bias,
                                                 float* __restrict__ out) {
    const __half* T = g_t;
    int v = blockIdx.x * 8 + (threadIdx.x >> 5);
    int lane = threadIdx.x & 31;
    int lo2 = lane * 2;

    float acc[2];
    float sw = g_selfw[v];
    {
        unsigned int raw = *(const unsigned int*)(T + (long)v * 64 + lo2);
        float2 p0 = __half22float2(*(__half2*)&raw);
        acc[0] = sw * p0.x; acc[1] = sw * p0.y;
    }

    int jb = g_rowptr[v];
    int je = g_rowptr[v + 1];
    int cnt = je - jb;

    int2 myE0 = make_int2(0, 0);
    int2 myE1 = make_int2(0, 0);
    if (lane < cnt) myE0 = g_edges[jb + lane];
    if (32 + lane < cnt) myE1 = g_edges[jb + 32 + lane];

    int rc = (cnt < 64) ? cnt : 64;
    int j = 0;
    for (; j + 1 < rc; j += 2) {
        int2 ea = (j < 32) ? shfl_e(myE0, j) : shfl_e(myE1, j - 32);
        int j1 = j + 1;
        int2 eb = (j1 < 32) ? shfl_e(myE0, j1) : shfl_e(myE1, j1 - 32);
        unsigned int r0 = *(const unsigned int*)(T + (long)ea.x * 64 + lo2);
        unsigned int r1 = *(const unsigned int*)(T + (long)eb.x * 64 + lo2);
        float w0 = __int_as_float(ea.y);
        float w1 = __int_as_float(eb.y);
        float2 a0 = __half22float2(*(__half2*)&r0);
        float2 b0 = __half22float2(*(__half2*)&r1);
        acc[0] = fmaf(w0, a0.x, acc[0]); acc[1] = fmaf(w0, a0.y, acc[1]);
        acc[0] = fmaf(w1, b0.x, acc[0]); acc[1] = fmaf(w1, b0.y, acc[1]);
    }
    if (j < rc) {
        int2 ea = (j < 32) ? shfl_e(myE0, j) : shfl_e(myE1, j - 32);
        unsigned int r0 = *(const unsigned int*)(T + (long)ea.x * 64 + lo2);
        float w0 = __int_as_float(ea.y);
        float2 a0 = __half22float2(*(__half2*)&r0);
        acc[0] = fmaf(w0, a0.x, acc[0]); acc[1] = fmaf(w0, a0.y, acc[1]);
    }
    for (int q = 64; q < cnt; q++) {
        int2 e0 = g_edges[jb + q];
        unsigned int r0 = *(const unsigned int*)(T + (long)e0.x * 64 + lo2);
        float w0 = __int_as_float(e0.y);
        float2 a0 = __half22float2(*(__half2*)&r0);
        acc[0] = fmaf(w0, a0.x, acc[0]); acc[1] = fmaf(w0, a0.y, acc[1]);
    }

    float2 o;
    o.x = acc[0] + bias[lo2];
    o.y = acc[1] + bias[lo2 + 1];
    *(float2*)(out + (long)v * 64 + lo2) = o;
}

// ---------------- launch ----------------
extern "C" void kernel_launch(void* const* d_in, const int* in_sizes, int n_in,
                              void* d_out, int out_size) {
    const void*  x      = d_in[0];
    const void*  ei     = d_in[1];
    const float* W_in   = (const float*)d_in[2];
    const float* W_conv = (const float*)d_in[3];
    const float* b_conv = (const float*)d_in[4];
    const float* W_dec  = (const float*)d_in[5];
    const float* b_dec  = (const float*)d_in[6];
    float* out = (float*)d_out;

    const int PAD = 136;
    const int SMEM_CONV = (2 * 128 + 128) * PAD * 2;  // 104448
    const int SMEM_DEC  = (2 * 128 + 64) * PAD * 2;   //  87040
    cudaFuncSetAttribute(k_mm_conv, cudaFuncAttributeMaxDynamicSharedMemorySize, SMEM_CONV);
    cudaFuncSetAttribute(k_mm_dec,  cudaFuncAttributeMaxDynamicSharedMemorySize, SMEM_DEC);

    k_init<<<(N_NODES + 255) / 256, 256>>>(x, ei);
    k_count<<<(N_EDGES + 255) / 256, 256>>>(ei);
    k_scan_dinv<<<1, 1024>>>();
    k_fill<<<(N_EDGES + 255) / 256, 256>>>(ei);
    k_prep_embed<<<96 + (N_NODES * 16 + 255) / 256, 256>>>(W_conv, W_dec, x, W_in);

    const int GEMM_BLOCKS = (N_NODES + 127) / 128;   // 313
    for (int it = 0; it < 4; it++) {
        k_mm_conv<<<GEMM_BLOCKS, 256, SMEM_CONV>>>();
        k_agg_conv<<<5000, 256>>>(b_conv);
    }
    k_mm_dec<<<GEMM_BLOCKS, 256, SMEM_DEC>>>();
    k_agg_dec<<<5000, 256>>>(b_dec, out);
}

// round 8
// speedup vs baseline: 1.1181x; 1.1181x over previous
#include <cuda_runtime.h>
#include <cuda_fp16.h>

#define N_NODES 40000
#define N_EDGES 640000
#define EMBED   128
#define NTYPE   64

// ---------------- scratch (static device globals; no allocs allowed) ----------------
__device__ __half g_t[N_NODES * EMBED];     // post-GEMM features, fp16
__device__ __half g_h[N_NODES * EMBED];     // layer input features, fp16
__device__ int    g_counts[N_NODES];
__device__ int    g_rowptr[N_NODES + 1];
__device__ int    g_cursor[N_NODES];
__device__ float  g_dinv[N_NODES];
__device__ float  g_selfw[N_NODES];
__device__ int2   g_edges[N_EDGES];
__device__ int    g_x64;
__device__ int    g_e64;
// weights as fp16 hi/lo, layout [n][k] (k contiguous)
__device__ __half g_Wch[128 * 128];
__device__ __half g_Wcl[128 * 128];
__device__ __half g_Wdh[64 * 128];
__device__ __half g_Wdl[64 * 128];

// ---------------- helpers ----------------
__device__ __forceinline__ int load_idx(const void* p, long long i, int is64) {
    if (is64) return (int)((const long long*)p)[i];
    return ((const int*)p)[i];
}

__device__ __forceinline__ unsigned int smem_u32(const void* p) {
    unsigned int a;
    asm("{ .reg .u64 t; cvta.to.shared.u64 t, %1; cvt.u32.u64 %0, t; }" : "=r"(a) : "l"(p));
    return a;
}

__device__ __forceinline__ void ldsm_x4(unsigned int& r0, unsigned int& r1,
                                        unsigned int& r2, unsigned int& r3,
                                        unsigned int addr) {
    asm volatile("ldmatrix.sync.aligned.m8n8.x4.shared.b16 {%0,%1,%2,%3}, [%4];"
                 : "=r"(r0), "=r"(r1), "=r"(r2), "=r"(r3) : "r"(addr));
}

__device__ __forceinline__ void ldsm_x2(unsigned int& r0, unsigned int& r1,
                                        unsigned int addr) {
    asm volatile("ldmatrix.sync.aligned.m8n8.x2.shared.b16 {%0,%1}, [%2];"
                 : "=r"(r0), "=r"(r1) : "r"(addr));
}

__device__ __forceinline__ void mma_fp16(float* d, unsigned int a0, unsigned int a1,
                                         unsigned int a2, unsigned int a3,
                                         unsigned int b0, unsigned int b1) {
    asm volatile(
        "mma.sync.aligned.m16n8k16.row.col.f32.f16.f16.f32 "
        "{%0,%1,%2,%3}, {%4,%5,%6,%7}, {%8,%9}, {%0,%1,%2,%3};"
        : "+f"(d[0]), "+f"(d[1]), "+f"(d[2]), "+f"(d[3])
        : "r"(a0), "r"(a1), "r"(a2), "r"(a3), "r"(b0), "r"(b1));
}

// ---------------- init: dtype detect (thread 0) + zero counts ----------------
__global__ void k_init(const void* xp, const void* ep) {
    int i = blockIdx.x * blockDim.x + threadIdx.x;
    if (i < N_NODES) g_counts[i] = 0;
    if (i == 0) {
        const unsigned int* w = (const unsigned int*)xp;
        int is64 = 1;
        for (int q = 0; q < 64; q++) {
            if (w[2 * q + 1] != 0u) { is64 = 0; break; }
        }
        g_x64 = is64;
        const unsigned int* we = (const unsigned int*)ep;
        int e64 = 1;
        for (int q = 0; q < 64; q++) {
            if (we[2 * q + 1] != 0u) { e64 = 0; break; }
        }
        g_e64 = e64;
    }
}

__global__ void k_count(const void* ei) {
    int e = blockIdx.x * blockDim.x + threadIdx.x;
    if (e < N_EDGES) {
        int d = load_idx(ei, (long long)N_EDGES + e, g_e64);
        atomicAdd(&g_counts[d], 1);
    }
}

// scan + dinv in one single-block kernel
__global__ void k_scan_dinv() {
    __shared__ int partial[1024];
    const int CH = (N_NODES + 1023) / 1024;   // 40
    int t = threadIdx.x;
    int base = t * CH;
    int cnt[CH];
    int s = 0;
    for (int i = 0; i < CH; i++) {
        int idx = base + i;
        int c = (idx < N_NODES) ? g_counts[idx] : 0;
        cnt[i] = c;
        s += c;
    }
    partial[t] = s;
    __syncthreads();
    for (int off = 1; off < 1024; off <<= 1) {
        int xv = (t >= off) ? partial[t - off] : 0;
        __syncthreads();
        partial[t] += xv;
        __syncthreads();
    }
    int run = partial[t] - s;
    for (int i = 0; i < CH; i++) {
        int idx = base + i;
        if (idx < N_NODES) {
            g_rowptr[idx] = run;
            g_cursor[idx] = run;
            run += cnt[i];
            float dv = rsqrtf((float)(cnt[i] + 1));
            g_dinv[idx] = dv;
            g_selfw[idx] = dv * dv;
        }
    }
    if (t == 1023) g_rowptr[N_NODES] = run;
}

__global__ void k_fill(const void* ei) {
    int e = blockIdx.x * blockDim.x + threadIdx.x;
    if (e < N_EDGES) {
        int is64 = g_e64;
        int s = load_idx(ei, e, is64);
        int d = load_idx(ei, (long long)N_EDGES + e, is64);
        int pos = atomicAdd(&g_cursor[d], 1);
        int2 v;
        v.x = s;
        v.y = __float_as_int(g_dinv[s] * g_dinv[d]);
        g_edges[pos] = v;
    }
}

// ---------------- fused weight-prep (fp16 hi/lo) + embedding gather (fp16) ----------
__global__ void k_prep_embed(const float* __restrict__ Wc, const float* __restrict__ Wd,
                             const void* xp, const float* __restrict__ Win) {
    if (blockIdx.x < 96) {
        int i = blockIdx.x * 256 + threadIdx.x;
        if (i < 16384) {
            int n = i >> 7;
            int k = i & 127;
            float v = Wc[k * 128 + n];
            __half h = __float2half_rn(v);
            __half l = __float2half_rn(v - __half2float(h));
            g_Wch[n * 128 + k] = h;
            g_Wcl[n * 128 + k] = l;
        } else {
            int j = i - 16384;
            int n = j >> 7;
            int k = j & 127;
            float v = Wd[k * 64 + n];
            __half h = __float2half_rn(v);
            __half l = __float2half_rn(v - __half2float(h));
            g_Wdh[n * 128 + k] = h;
            g_Wdl[n * 128 + k] = l;
        }
    } else {
        int id = (blockIdx.x - 96) * 256 + threadIdx.x;
        if (id < N_NODES * 16) {
            int v = id >> 4;
            int k0 = (id & 15) * 8;
            int row = load_idx(xp, v, g_x64);
            const float* src = Win + (long)row * EMBED + k0;
            __half hv[8];
            #pragma unroll
            for (int q = 0; q < 8; q++) {
                hv[q] = __float2half_rn(src[q]);
            }
            *(uint4*)(g_h + (long)v * EMBED + k0) = *(uint4*)hv;
        }
    }
}

// ---------------- tensor-core GEMM (mma.sync fp16, 2 passes: A*Wh + A*Wl) ----------
template <int NCOL>
__device__ __forceinline__ void mma_gemm_body(const __half* __restrict__ Wh,
                                              const __half* __restrict__ Wl,
                                              __half* __restrict__ C) {
    const int PAD = 136;
    const int NT = NCOL / 8;
    extern __shared__ unsigned short sm[];
    unsigned short* As = sm;                       // [128][PAD]
    unsigned short* Bs = As + 128 * PAD;           // [NCOL][PAD], Wh then Wl

    int tid = threadIdx.x;
    int wid = tid >> 5;
    int lane = tid & 31;
    int row0 = blockIdx.x * 128;

    for (int i = tid; i < 2048; i += 256) {
        int r = i >> 4;
        int k0 = (i & 15) * 8;
        int gr = row0 + r;
        uint4 va = make_uint4(0u, 0u, 0u, 0u);
        if (gr < N_NODES) {
            va = *(const uint4*)(g_h + (long)gr * EMBED + k0);
        }
        *(uint4*)(As + r * PAD + k0) = va;
    }
    for (int i = tid; i < NCOL * 16; i += 256) {
        int r = i >> 4;
        int k0 = (i & 15) * 8;
        *(uint4*)(Bs + r * PAD + k0) = *(const uint4*)((const unsigned short*)Wh + r * 128 + k0);
    }
    __syncthreads();

    int m0 = wid * 16;
    float acc[NT][4];
    #pragma unroll
    for (int j = 0; j < NT; j++) {
        #pragma unroll
        for (int q = 0; q < 4; q++) acc[j][q] = 0.0f;
    }

    const unsigned int sb = smem_u32(sm);
    unsigned int a_off = (unsigned int)((m0 + (lane & 15)) * PAD + (lane >> 4) * 8) * 2u;
    unsigned int b_off = (unsigned int)(((lane & 15) & 7) * PAD + ((lane & 15) >> 3) * 8) * 2u;
    unsigned int a_b = sb + a_off;
    unsigned int b_b = sb + (unsigned int)(128 * PAD * 2) + b_off;

    // pass 1: A * Wh
    #pragma unroll
    for (int ks = 0; ks < 8; ks++) {
        unsigned int h0, h1, h2, h3;
        ldsm_x4(h0, h1, h2, h3, a_b + (unsigned int)(ks * 32));
        #pragma unroll
        for (int j = 0; j < NT; j++) {
            unsigned int b0, b1;
            ldsm_x2(b0, b1, b_b + (unsigned int)(j * 8 * PAD * 2 + ks * 32));
            mma_fp16(acc[j], h0, h1, h2, h3, b0, b1);
        }
    }
    // restage B with Wl
    __syncthreads();
    for (int i = tid; i < NCOL * 16; i += 256) {
        int r = i >> 4;
        int k0 = (i & 15) * 8;
        *(uint4*)(Bs + r * PAD + k0) = *(const uint4*)((const unsigned short*)Wl + r * 128 + k0);
    }
    __syncthreads();
    // pass 2: A * Wl
    #pragma unroll
    for (int ks = 0; ks < 8; ks++) {
        unsigned int h0, h1, h2, h3;
        ldsm_x4(h0, h1, h2, h3, a_b + (unsigned int)(ks * 32));
        #pragma unroll
        for (int j = 0; j < NT; j++) {
            unsigned int b0, b1;
            ldsm_x2(b0, b1, b_b + (unsigned int)(j * 8 * PAD * 2 + ks * 32));
            mma_fp16(acc[j], h0, h1, h2, h3, b0, b1);
        }
    }

    // epilogue: fp16 stores
    int mrow = m0 + (lane >> 2);
    int nc0 = (lane & 3) * 2;
    int gr0 = row0 + mrow;
    int gr1 = gr0 + 8;
    #pragma unroll
    for (int j = 0; j < NT; j++) {
        if (gr0 < N_NODES) {
            *(__half2*)(C + (long)gr0 * NCOL + j * 8 + nc0) =
                __floats2half2_rn(acc[j][0], acc[j][1]);
        }
        if (gr1 < N_NODES) {
            *(__half2*)(C + (long)gr1 * NCOL + j * 8 + nc0) =
                __floats2half2_rn(acc[j][2], acc[j][3]);
        }
    }
}

__global__ void __launch_bounds__(256, 3) k_mm_conv() {
    mma_gemm_body<128>(g_Wch, g_Wcl, g_t);
}
__global__ void __launch_bounds__(256, 3) k_mm_dec() {
    mma_gemm_body<64>(g_Wdh, g_Wdl, g_t);
}

// ---------------- aggregation (R5 form: fp16 gathers, fp32 accumulate, unroll 2) ----
__global__ void __launch_bounds__(256) k_agg_conv(const float* __restrict__ bias) {
    const __half* T = g_t;
    int v = blockIdx.x * 8 + (threadIdx.x >> 5);
    int lane = threadIdx.x & 31;
    int lo4 = lane * 4;

    float acc[4];
    float sw = g_selfw[v];
    {
        uint2 raw = *(const uint2*)(T + (long)v * 128 + lo4);
        float2 p0 = __half22float2(*(__half2*)&raw.x);
        float2 p1 = __half22float2(*(__half2*)&raw.y);
        acc[0] = sw * p0.x; acc[1] = sw * p0.y;
        acc[2] = sw * p1.x; acc[3] = sw * p1.y;
    }

    int jb = g_rowptr[v];
    int je = g_rowptr[v + 1];
    int j = jb;
    for (; j + 1 < je; j += 2) {
        int2 e0 = g_edges[j];
        int2 e1 = g_edges[j + 1];
        uint2 r0 = *(const uint2*)(T + (long)e0.x * 128 + lo4);
        uint2 r1 = *(const uint2*)(T + (long)e1.x * 128 + lo4);
        float w0 = __int_as_float(e0.y);
        float w1 = __int_as_float(e1.y);
        float2 a0 = __half22float2(*(__half2*)&r0.x);
        float2 a1 = __half22float2(*(__half2*)&r0.y);
        float2 b0 = __half22float2(*(__half2*)&r1.x);
        float2 b1 = __half22float2(*(__half2*)&r1.y);
        acc[0] = fmaf(w0, a0.x, acc[0]); acc[1] = fmaf(w0, a0.y, acc[1]);
        acc[2] = fmaf(w0, a1.x, acc[2]); acc[3] = fmaf(w0, a1.y, acc[3]);
        acc[0] = fmaf(w1, b0.x, acc[0]); acc[1] = fmaf(w1, b0.y, acc[1]);
        acc[2] = fmaf(w1, b1.x, acc[2]); acc[3] = fmaf(w1, b1.y, acc[3]);
    }
    if (j < je) {
        int2 e0 = g_edges[j];
        uint2 r0 = *(const uint2*)(T + (long)e0.x * 128 + lo4);
        float w0 = __int_as_float(e0.y);
        float2 a0 = __half22float2(*(__half2*)&r0.x);
        float2 a1 = __half22float2(*(__half2*)&r0.y);
        acc[0] = fmaf(w0, a0.x, acc[0]); acc[1] = fmaf(w0, a0.y, acc[1]);
        acc[2] = fmaf(w0, a1.x, acc[2]); acc[3] = fmaf(w0, a1.y, acc[3]);
    }

    __half hv[4];
    #pragma unroll
    for (int i = 0; i < 4; i++) {
        float a = fmaxf(acc[i] + bias[lo4 + i], 0.0f);
        hv[i] = __float2half_rn(a);
    }
    *(uint2*)(g_h + (long)v * 128 + lo4) = *(uint2*)hv;
}

__global__ void __launch_bounds__(256) k_agg_dec(const float* __restrict__ bias,
                                                 float* __restrict__ out) {
    const __half* T = g_t;
    int v = blockIdx.x * 8 + (threadIdx.x >> 5);
    int lane = threadIdx.x & 31;
    int lo2 = lane * 2;

    float acc[2];
    float sw = g_selfw[v];
    {
        unsigned int raw = *(const unsigned int*)(T + (long)v * 64 + lo2);
        float2 p0 = __half22float2(*(__half2*)&raw);
        acc[0] = sw * p0.x; acc[1] = sw * p0.y;
    }

    int jb = g_rowptr[v];
    int je = g_rowptr[v + 1];
    int j = jb;
    for (; j + 1 < je; j += 2) {
        int2 e0 = g_edges[j];
        int2 e1 = g_edges[j + 1];
        unsigned int r0 = *(const unsigned int*)(T + (long)e0.x * 64 + lo2);
        unsigned int r1 = *(const unsigned int*)(T + (long)e1.x * 64 + lo2);
        float w0 = __int_as_float(e0.y);
        float w1 = __int_as_float(e1.y);
        float2 a0 = __half22float2(*(__half2*)&r0);
        float2 b0 = __half22float2(*(__half2*)&r1);
        acc[0] = fmaf(w0, a0.x, acc[0]); acc[1] = fmaf(w0, a0.y, acc[1]);
        acc[0] = fmaf(w1, b0.x, acc[0]); acc[1] = fmaf(w1, b0.y, acc[1]);
    }
    if (j < je) {
        int2 e0 = g_edges[j];
        unsigned int r0 = *(const unsigned int*)(T + (long)e0.x * 64 + lo2);
        float w0 = __int_as_float(e0.y);
        float2 a0 = __half22float2(*(__half2*)&r0);
        acc[0] = fmaf(w0, a0.x, acc[0]); acc[1] = fmaf(w0, a0.y, acc[1]);
    }

    float2 o;
    o.x = acc[0] + bias[lo2];
    o.y = acc[1] + bias[lo2 + 1];
    *(float2*)(out + (long)v * 64 + lo2) = o;
}

// ---------------- launch ----------------
extern "C" void kernel_launch(void* const* d_in, const int* in_sizes, int n_in,
                              void* d_out, int out_size) {
    const void*  x      = d_in[0];
    const void*  ei     = d_in[1];
    const float* W_in   = (const float*)d_in[2];
    const float* W_conv = (const float*)d_in[3];
    const float* b_conv = (const float*)d_in[4];
    const float* W_dec  = (const float*)d_in[5];
    const float* b_dec  = (const float*)d_in[6];
    float* out = (float*)d_out;

    const int PAD = 136;
    const int SMEM_CONV = (128 + 128) * PAD * 2;  // 69632
    const int SMEM_DEC  = (128 + 64) * PAD * 2;   // 52224
    cudaFuncSetAttribute(k_mm_conv, cudaFuncAttributeMaxDynamicSharedMemorySize, SMEM_CONV);
    cudaFuncSetAttribute(k_mm_dec,  cudaFuncAttributeMaxDynamicSharedMemorySize, SMEM_DEC);

    k_init<<<(N_NODES + 255) / 256, 256>>>(x, ei);
    k_count<<<(N_EDGES + 255) / 256, 256>>>(ei);
    k_scan_dinv<<<1, 1024>>>();
    k_fill<<<(N_EDGES + 255) / 256, 256>>>(ei);
    k_prep_embed<<<96 + (N_NODES * 16 + 255) / 256, 256>>>(W_conv, W_dec, x, W_in);

    const int GEMM_BLOCKS = (N_NODES + 127) / 128;   // 313
    for (int it = 0; it < 4; it++) {
        k_mm_conv<<<GEMM_BLOCKS, 256, SMEM_CONV>>>();
        k_agg_conv<<<5000, 256>>>(b_conv);
    }
    k_mm_dec<<<GEMM_BLOCKS, 256, SMEM_DEC>>>();
    k_agg_dec<<<5000, 256>>>(b_dec, out);
}

// round 9
// speedup vs baseline: 1.1184x; 1.0003x over previous
#include <cuda_runtime.h>
#include <cuda_fp16.h>

#define N_NODES 40000
#define N_EDGES 640000
#define EMBED   128
#define NTYPE   64

// ---------------- scratch (static device globals; no allocs allowed) ----------------
__device__ __half g_t[N_NODES * EMBED];     // post-GEMM features, fp16
__device__ __half g_h[N_NODES * EMBED];     // layer input features, fp16
__device__ int    g_counts[N_NODES];
__device__ int    g_rowptr[N_NODES + 1];
__device__ int    g_cursor[N_NODES];
__device__ float  g_dinv[N_NODES];
__device__ float  g_selfw[N_NODES];
__device__ int2   g_edges[N_EDGES];
__device__ int    g_x64;
__device__ int    g_e64;
// weights as fp16 hi/lo, layout [n][k] (k contiguous)
__device__ __half g_Wch[128 * 128];
__device__ __half g_Wcl[128 * 128];
__device__ __half g_Wdh[64 * 128];
__device__ __half g_Wdl[64 * 128];

// ---------------- helpers ----------------
__device__ __forceinline__ int load_idx(const void* p, long long i, int is64) {
    if (is64) return (int)((const long long*)p)[i];
    return ((const int*)p)[i];
}

__device__ __forceinline__ unsigned int smem_u32(const void* p) {
    unsigned int a;
    asm("{ .reg .u64 t; cvta.to.shared.u64 t, %1; cvt.u32.u64 %0, t; }" : "=r"(a) : "l"(p));
    return a;
}

__device__ __forceinline__ void ldsm_x4(unsigned int& r0, unsigned int& r1,
                                        unsigned int& r2, unsigned int& r3,
                                        unsigned int addr) {
    asm volatile("ldmatrix.sync.aligned.m8n8.x4.shared.b16 {%0,%1,%2,%3}, [%4];"
                 : "=r"(r0), "=r"(r1), "=r"(r2), "=r"(r3) : "r"(addr));
}

__device__ __forceinline__ void mma_fp16(float* d, unsigned int a0, unsigned int a1,
                                         unsigned int a2, unsigned int a3,
                                         unsigned int b0, unsigned int b1) {
    asm volatile(
        "mma.sync.aligned.m16n8k16.row.col.f32.f16.f16.f32 "
        "{%0,%1,%2,%3}, {%4,%5,%6,%7}, {%8,%9}, {%0,%1,%2,%3};"
        : "+f"(d[0]), "+f"(d[1]), "+f"(d[2]), "+f"(d[3])
        : "r"(a0), "r"(a1), "r"(a2), "r"(a3), "r"(b0), "r"(b1));
}

// ---------------- init: dtype detect (thread 0) + zero counts ----------------
__global__ void k_init(const void* xp, const void* ep) {
    int i = blockIdx.x * blockDim.x + threadIdx.x;
    if (i < N_NODES) g_counts[i] = 0;
    if (i == 0) {
        const unsigned int* w = (const unsigned int*)xp;
        int is64 = 1;
        for (int q = 0; q < 64; q++) {
            if (w[2 * q + 1] != 0u) { is64 = 0; break; }
        }
        g_x64 = is64;
        const unsigned int* we = (const unsigned int*)ep;
        int e64 = 1;
        for (int q = 0; q < 64; q++) {
            if (we[2 * q + 1] != 0u) { e64 = 0; break; }
        }
        g_e64 = e64;
    }
}

__global__ void k_count(const void* ei) {
    int e = blockIdx.x * blockDim.x + threadIdx.x;
    if (e < N_EDGES) {
        int d = load_idx(ei, (long long)N_EDGES + e, g_e64);
        atomicAdd(&g_counts[d], 1);
    }
}

// scan + dinv in one single-block kernel
__global__ void k_scan_dinv() {
    __shared__ int partial[1024];
    const int CH = (N_NODES + 1023) / 1024;   // 40
    int t = threadIdx.x;
    int base = t * CH;
    int cnt[CH];
    int s = 0;
    for (int i = 0; i < CH; i++) {
        int idx = base + i;
        int c = (idx < N_NODES) ? g_counts[idx] : 0;
        cnt[i] = c;
        s += c;
    }
    partial[t] = s;
    __syncthreads();
    for (int off = 1; off < 1024; off <<= 1) {
        int xv = (t >= off) ? partial[t - off] : 0;
        __syncthreads();
        partial[t] += xv;
        __syncthreads();
    }
    int run = partial[t] - s;
    for (int i = 0; i < CH; i++) {
        int idx = base + i;
        if (idx < N_NODES) {
            g_rowptr[idx] = run;
            g_cursor[idx] = run;
            run += cnt[i];
            float dv = rsqrtf((float)(cnt[i] + 1));
            g_dinv[idx] = dv;
            g_selfw[idx] = dv * dv;
        }
    }
    if (t == 1023) g_rowptr[N_NODES] = run;
}

__global__ void k_fill(const void* ei) {
    int e = blockIdx.x * blockDim.x + threadIdx.x;
    if (e < N_EDGES) {
        int is64 = g_e64;
        int s = load_idx(ei, e, is64);
        int d = load_idx(ei, (long long)N_EDGES + e, is64);
        int pos = atomicAdd(&g_cursor[d], 1);
        int2 v;
        v.x = s;
        v.y = __float_as_int(g_dinv[s] * g_dinv[d]);
        g_edges[pos] = v;
    }
}

// ---------------- fused weight-prep (fp16 hi/lo) + embedding gather (fp16) ----------
__global__ void k_prep_embed(const float* __restrict__ Wc, const float* __restrict__ Wd,
                             const void* xp, const float* __restrict__ Win) {
    if (blockIdx.x < 96) {
        int i = blockIdx.x * 256 + threadIdx.x;
        if (i < 16384) {
            int n = i >> 7;
            int k = i & 127;
            float v = Wc[k * 128 + n];
            __half h = __float2half_rn(v);
            __half l = __float2half_rn(v - __half2float(h));
            g_Wch[n * 128 + k] = h;
            g_Wcl[n * 128 + k] = l;
        } else {
            int j = i - 16384;
            int n = j >> 7;
            int k = j & 127;
            float v = Wd[k * 64 + n];
            __half h = __float2half_rn(v);
            __half l = __float2half_rn(v - __half2float(h));
            g_Wdh[n * 128 + k] = h;
            g_Wdl[n * 128 + k] = l;
        }
    } else {
        int id = (blockIdx.x - 96) * 256 + threadIdx.x;
        if (id < N_NODES * 16) {
            int v = id >> 4;
            int k0 = (id & 15) * 8;
            int row = load_idx(xp, v, g_x64);
            const float* src = Win + (long)row * EMBED + k0;
            __half hv[8];
            #pragma unroll
            for (int q = 0; q < 8; q++) {
                hv[q] = __float2half_rn(src[q]);
            }
            *(uint4*)(g_h + (long)v * EMBED + k0) = *(uint4*)hv;
        }
    }
}

// ---------------- tensor-core GEMM (mma.sync fp16, 2 passes: A*Wh + A*Wl) ----------
// B loaded with ldmatrix.x4 = two n-tiles per instruction.
template <int NCOL>
__device__ __forceinline__ void mma_gemm_body(const __half* __restrict__ Wh,
                                              const __half* __restrict__ Wl,
                                              __half* __restrict__ C) {
    const int PAD = 136;
    const int NT = NCOL / 8;
    extern __shared__ unsigned short sm[];
    unsigned short* As = sm;                       // [128][PAD]
    unsigned short* Bs = As + 128 * PAD;           // [NCOL][PAD], Wh then Wl

    int tid = threadIdx.x;
    int wid = tid >> 5;
    int lane = tid & 31;
    int row0 = blockIdx.x * 128;

    for (int i = tid; i < 2048; i += 256) {
        int r = i >> 4;
        int k0 = (i & 15) * 8;
        int gr = row0 + r;
        uint4 va = make_uint4(0u, 0u, 0u, 0u);
        if (gr < N_NODES) {
            va = *(const uint4*)(g_h + (long)gr * EMBED + k0);
        }
        *(uint4*)(As + r * PAD + k0) = va;
    }
    for (int i = tid; i < NCOL * 16; i += 256) {
        int r = i >> 4;
        int k0 = (i & 15) * 8;
        *(uint4*)(Bs + r * PAD + k0) = *(const uint4*)((const unsigned short*)Wh + r * 128 + k0);
    }
    __syncthreads();

    int m0 = wid * 16;
    float acc[NT][4];
    #pragma unroll
    for (int j = 0; j < NT; j++) {
        #pragma unroll
        for (int q = 0; q < 4; q++) acc[j][q] = 0.0f;
    }

    const unsigned int sb = smem_u32(sm);
    // A x4: lanes 0-15 rows m0..m0+15 (k0 half), lanes 16-31 same rows k8 half
    unsigned int a_off = (unsigned int)((m0 + (lane & 15)) * PAD + (lane >> 4) * 8) * 2u;
    // B x4 (two n-tiles): lanes 0-15 n-tile j rows (k-half by lane>>3),
    //                     lanes 16-31 n-tile j+1 rows
    unsigned int b4_off = (unsigned int)(((lane & 7) + ((lane >> 4) * 8)) * PAD +
                                         (((lane >> 3) & 1) * 8)) * 2u;
    unsigned int a_b = sb + a_off;
    unsigned int b_b = sb + (unsigned int)(128 * PAD * 2) + b4_off;

    // pass 1: A * Wh
    #pragma unroll
    for (int ks = 0; ks < 8; ks++) {
        unsigned int h0, h1, h2, h3;
        ldsm_x4(h0, h1, h2, h3, a_b + (unsigned int)(ks * 32));
        #pragma unroll
        for (int j = 0; j < NT; j += 2) {
            unsigned int b0, b1, b2, b3;
            ldsm_x4(b0, b1, b2, b3, b_b + (unsigned int)(j * 8 * PAD * 2 + ks * 32));
            mma_fp16(acc[j],     h0, h1, h2, h3, b0, b1);
            mma_fp16(acc[j + 1], h0, h1, h2, h3, b2, b3);
        }
    }
    // restage B with Wl
    __syncthreads();
    for (int i = tid; i < NCOL * 16; i += 256) {
        int r = i >> 4;
        int k0 = (i & 15) * 8;
        *(uint4*)(Bs + r * PAD + k0) = *(const uint4*)((const unsigned short*)Wl + r * 128 + k0);
    }
    __syncthreads();
    // pass 2: A * Wl
    #pragma unroll
    for (int ks = 0; ks < 8; ks++) {
        unsigned int h0, h1, h2, h3;
        ldsm_x4(h0, h1, h2, h3, a_b + (unsigned int)(ks * 32));
        #pragma unroll
        for (int j = 0; j < NT; j += 2) {
            unsigned int b0, b1, b2, b3;
            ldsm_x4(b0, b1, b2, b3, b_b + (unsigned int)(j * 8 * PAD * 2 + ks * 32));
            mma_fp16(acc[j],     h0, h1, h2, h3, b0, b1);
            mma_fp16(acc[j + 1], h0, h1, h2, h3, b2, b3);
        }
    }

    // epilogue: fp16 stores
    int mrow = m0 + (lane >> 2);
    int nc0 = (lane & 3) * 2;
    int gr0 = row0 + mrow;
    int gr1 = gr0 + 8;
    #pragma unroll
    for (int j = 0; j < NT; j++) {
        if (gr0 < N_NODES) {
            *(__half2*)(C + (long)gr0 * NCOL + j * 8 + nc0) =
                __floats2half2_rn(acc[j][0], acc[j][1]);
        }
        if (gr1 < N_NODES) {
            *(__half2*)(C + (long)gr1 * NCOL + j * 8 + nc0) =
                __floats2half2_rn(acc[j][2], acc[j][3]);
        }
    }
}

__global__ void __launch_bounds__(256, 3) k_mm_conv() {
    mma_gemm_body<128>(g_Wch, g_Wcl, g_t);
}
__global__ void __launch_bounds__(256, 3) k_mm_dec() {
    mma_gemm_body<64>(g_Wdh, g_Wdl, g_t);
}

// ---------------- aggregation (fp16 gathers, fp32 accumulate, unroll 2) ----
__global__ void __launch_bounds__(256) k_agg_conv(const float* __restrict__ bias) {
    const __half* T = g_t;
    int v = blockIdx.x * 8 + (threadIdx.x >> 5);
    int lane = threadIdx.x & 31;
    int lo4 = lane * 4;

    float acc[4];
    float sw = g_selfw[v];
    {
        uint2 raw = *(const uint2*)(T + (long)v * 128 + lo4);
        float2 p0 = __half22float2(*(__half2*)&raw.x);
        float2 p1 = __half22float2(*(__half2*)&raw.y);
        acc[0] = sw * p0.x; acc[1] = sw * p0.y;
        acc[2] = sw * p1.x; acc[3] = sw * p1.y;
    }

    int jb = g_rowptr[v];
    int je = g_rowptr[v + 1];
    int j = jb;
    for (; j + 1 < je; j += 2) {
        int2 e0 = g_edges[j];
        int2 e1 = g_edges[j + 1];
        uint2 r0 = *(const uint2*)(T + (long)e0.x * 128 + lo4);
        uint2 r1 = *(const uint2*)(T + (long)e1.x * 128 + lo4);
        float w0 = __int_as_float(e0.y);
        float w1 = __int_as_float(e1.y);
        float2 a0 = __half22float2(*(__half2*)&r0.x);
        float2 a1 = __half22float2(*(__half2*)&r0.y);
        float2 b0 = __half22float2(*(__half2*)&r1.x);
        float2 b1 = __half22float2(*(__half2*)&r1.y);
        acc[0] = fmaf(w0, a0.x, acc[0]); acc[1] = fmaf(w0, a0.y, acc[1]);
        acc[2] = fmaf(w0, a1.x, acc[2]); acc[3] = fmaf(w0, a1.y, acc[3]);
        acc[0] = fmaf(w1, b0.x, acc[0]); acc[1] = fmaf(w1, b0.y, acc[1]);
        acc[2] = fmaf(w1, b1.x, acc[2]); acc[3] = fmaf(w1, b1.y, acc[3]);
    }
    if (j < je) {
        int2 e0 = g_edges[j];
        uint2 r0 = *(const uint2*)(T + (long)e0.x * 128 + lo4);
        float w0 = __int_as_float(e0.y);
        float2 a0 = __half22float2(*(__half2*)&r0.x);
        float2 a1 = __half22float2(*(__half2*)&r0.y);
        acc[0] = fmaf(w0, a0.x, acc[0]); acc[1] = fmaf(w0, a0.y, acc[1]);
        acc[2] = fmaf(w0, a1.x, acc[2]); acc[3] = fmaf(w0, a1.y, acc[3]);
    }

    __half hv[4];
    #pragma unroll
    for (int i = 0; i < 4; i++) {
        float a = fmaxf(acc[i] + bias[lo4 + i], 0.0f);
        hv[i] = __float2half_rn(a);
    }
    *(uint2*)(g_h + (long)v * 128 + lo4) = *(uint2*)hv;
}

__global__ void __launch_bounds__(256) k_agg_dec(const float* __restrict__ bias,
                                                 float* __restrict__ out) {
    const __half* T = g_t;
    int v = blockIdx.x * 8 + (threadIdx.x >> 5);
    int lane = threadIdx.x & 31;
    int lo2 = lane * 2;

    float acc[2];
    float sw = g_selfw[v];
    {
        unsigned int raw = *(const unsigned int*)(T + (long)v * 64 + lo2);
        float2 p0 = __half22float2(*(__half2*)&raw);
        acc[0] = sw * p0.x; acc[1] = sw * p0.y;
    }

    int jb = g_rowptr[v];
    int je = g_rowptr[v + 1];
    int j = jb;
    for (; j + 1 < je; j += 2) {
        int2 e0 = g_edges[j];
        int2 e1 = g_edges[j + 1];
        unsigned int r0 = *(const unsigned int*)(T + (long)e0.x * 64 + lo2);
        unsigned int r1 = *(const unsigned int*)(T + (long)e1.x * 64 + lo2);
        float w0 = __int_as_float(e0.y);
        float w1 = __int_as_float(e1.y);
        float2 a0 = __half22float2(*(__half2*)&r0);
        float2 b0 = __half22float2(*(__half2*)&r1);
        acc[0] = fmaf(w0, a0.x, acc[0]); acc[1] = fmaf(w0, a0.y, acc[1]);
        acc[0] = fmaf(w1, b0.x, acc[0]); acc[1] = fmaf(w1, b0.y, acc[1]);
    }
    if (j < je) {
        int2 e0 = g_edges[j];
        unsigned int r0 = *(const unsigned int*)(T + (long)e0.x * 64 + lo2);
        float w0 = __int_as_float(e0.y);
        float2 a0 = __half22float2(*(__half2*)&r0);
        acc[0] = fmaf(w0, a0.x, acc[0]); acc[1] = fmaf(w0, a0.y, acc[1]);
    }

    float2 o;
    o.x = acc[0] + bias[lo2];
    o.y = acc[1] + bias[lo2 + 1];
    *(float2*)(out + (long)v * 64 + lo2) = o;
}

// ---------------- launch ----------------
// Order chosen so k_mm_conv is the 4th launch (ncu capture slot) while keeping
// all dependencies: prep_embed needs init; mm_conv needs prep_embed;
// agg needs scan_dinv+fill (which precede the first agg).
extern "C" void kernel_launch(void* const* d_in, const int* in_sizes, int n_in,
                              void* d_out, int out_size) {
    const void*  x      = d_in[0];
    const void*  ei     = d_in[1];
    const float* W_in   = (const float*)d_in[2];
    const float* W_conv = (const float*)d_in[3];
    const float* b_conv = (const float*)d_in[4];
    const float* W_dec  = (const float*)d_in[5];
    const float* b_dec  = (const float*)d_in[6];
    float* out = (float*)d_out;

    const int PAD = 136;
    const int SMEM_CONV = (128 + 128) * PAD * 2;  // 69632
    const int SMEM_DEC  = (128 + 64) * PAD * 2;   // 52224
    cudaFuncSetAttribute(k_mm_conv, cudaFuncAttributeMaxDynamicSharedMemorySize, SMEM_CONV);
    cudaFuncSetAttribute(k_mm_dec,  cudaFuncAttributeMaxDynamicSharedMemorySize, SMEM_DEC);

    const int GEMM_BLOCKS = (N_NODES + 127) / 128;   // 313

    k_init<<<(N_NODES + 255) / 256, 256>>>(x, ei);                                 // 1
    k_count<<<(N_EDGES + 255) / 256, 256>>>(ei);                                   // 2
    k_prep_embed<<<96 + (N_NODES * 16 + 255) / 256, 256>>>(W_conv, W_dec, x, W_in);// 3
    k_mm_conv<<<GEMM_BLOCKS, 256, SMEM_CONV>>>();                                  // 4 (ncu)
    k_scan_dinv<<<1, 1024>>>();                                                    // 5
    k_fill<<<(N_EDGES + 255) / 256, 256>>>(ei);                                    // 6
    k_agg_conv<<<5000, 256>>>(b_conv);                                             // 7

    for (int it = 0; it < 3; it++) {
        k_mm_conv<<<GEMM_BLOCKS, 256, SMEM_CONV>>>();
        k_agg_conv<<<5000, 256>>>(b_conv);
    }
    k_mm_dec<<<GEMM_BLOCKS, 256, SMEM_DEC>>>();
    k_agg_dec<<<5000, 256>>>(b_dec, out);
}

// round 10
// speedup vs baseline: 1.1382x; 1.0177x over previous
#include <cuda_runtime.h>
#include <cuda_fp16.h>

#define N_NODES 40000
#define N_EDGES 640000
#define EMBED   128
#define NTYPE   64

// ---------------- scratch (static device globals; no allocs allowed) ----------------
__device__ __half g_t[N_NODES * EMBED];     // post-GEMM features, fp16
__device__ __half g_h[N_NODES * EMBED];     // layer input features, fp16
__device__ int    g_counts[N_NODES];
__device__ int    g_rowptr[N_NODES + 1];
__device__ int    g_cursor[N_NODES];
__device__ float  g_dinv[N_NODES];
__device__ float  g_selfw[N_NODES];
__device__ int2   g_edges[N_EDGES];
__device__ int    g_x64;
__device__ int    g_e64;
// weights as fp16 hi/lo, layout [n][k] (k contiguous)
__device__ __half g_Wch[128 * 128];
__device__ __half g_Wcl[128 * 128];
__device__ __half g_Wdh[64 * 128];
__device__ __half g_Wdl[64 * 128];

// ---------------- helpers ----------------
__device__ __forceinline__ int load_idx(const void* p, long long i, int is64) {
    if (is64) return (int)((const long long*)p)[i];
    return ((const int*)p)[i];
}

__device__ __forceinline__ unsigned int smem_u32(const void* p) {
    unsigned int a;
    asm("{ .reg .u64 t; cvta.to.shared.u64 t, %1; cvt.u32.u64 %0, t; }" : "=r"(a) : "l"(p));
    return a;
}

__device__ __forceinline__ void ldsm_x4(unsigned int& r0, unsigned int& r1,
                                        unsigned int& r2, unsigned int& r3,
                                        unsigned int addr) {
    asm volatile("ldmatrix.sync.aligned.m8n8.x4.shared.b16 {%0,%1,%2,%3}, [%4];"
                 : "=r"(r0), "=r"(r1), "=r"(r2), "=r"(r3) : "r"(addr));
}

__device__ __forceinline__ void mma_fp16(float* d, unsigned int a0, unsigned int a1,
                                         unsigned int a2, unsigned int a3,
                                         unsigned int b0, unsigned int b1) {
    asm volatile(
        "mma.sync.aligned.m16n8k16.row.col.f32.f16.f16.f32 "
        "{%0,%1,%2,%3}, {%4,%5,%6,%7}, {%8,%9}, {%0,%1,%2,%3};"
        : "+f"(d[0]), "+f"(d[1]), "+f"(d[2]), "+f"(d[3])
        : "r"(a0), "r"(a1), "r"(a2), "r"(a3), "r"(b0), "r"(b1));
}

// ---------------- init: dtype detect (thread 0) + zero counts ----------------
__global__ void k_init(const void* xp, const void* ep) {
    int i = blockIdx.x * blockDim.x + threadIdx.x;
    if (i < N_NODES) g_counts[i] = 0;
    if (i == 0) {
        const unsigned int* w = (const unsigned int*)xp;
        int is64 = 1;
        for (int q = 0; q < 64; q++) {
            if (w[2 * q + 1] != 0u) { is64 = 0; break; }
        }
        g_x64 = is64;
        const unsigned int* we = (const unsigned int*)ep;
        int e64 = 1;
        for (int q = 0; q < 64; q++) {
            if (we[2 * q + 1] != 0u) { e64 = 0; break; }
        }
        g_e64 = e64;
    }
}

__global__ void k_count(const void* ei) {
    int e = blockIdx.x * blockDim.x + threadIdx.x;
    if (e < N_EDGES) {
        int d = load_idx(ei, (long long)N_EDGES + e, g_e64);
        atomicAdd(&g_counts[d], 1);
    }
}

// scan + dinv in one single-block kernel
__global__ void k_scan_dinv() {
    __shared__ int partial[1024];
    const int CH = (N_NODES + 1023) / 1024;   // 40
    int t = threadIdx.x;
    int base = t * CH;
    int cnt[CH];
    int s = 0;
    for (int i = 0; i < CH; i++) {
        int idx = base + i;
        int c = (idx < N_NODES) ? g_counts[idx] : 0;
        cnt[i] = c;
        s += c;
    }
    partial[t] = s;
    __syncthreads();
    for (int off = 1; off < 1024; off <<= 1) {
        int xv = (t >= off) ? partial[t - off] : 0;
        __syncthreads();
        partial[t] += xv;
        __syncthreads();
    }
    int run = partial[t] - s;
    for (int i = 0; i < CH; i++) {
        int idx = base + i;
        if (idx < N_NODES) {
            g_rowptr[idx] = run;
            g_cursor[idx] = run;
            run += cnt[i];
            float dv = rsqrtf((float)(cnt[i] + 1));
            g_dinv[idx] = dv;
            g_selfw[idx] = dv * dv;
        }
    }
    if (t == 1023) g_rowptr[N_NODES] = run;
}

__global__ void k_fill(const void* ei) {
    int e = blockIdx.x * blockDim.x + threadIdx.x;
    if (e < N_EDGES) {
        int is64 = g_e64;
        int s = load_idx(ei, e, is64);
        int d = load_idx(ei, (long long)N_EDGES + e, is64);
        int pos = atomicAdd(&g_cursor[d], 1);
        int2 v;
        v.x = s;
        v.y = __float_as_int(g_dinv[s] * g_dinv[d]);
        g_edges[pos] = v;
    }
}

// ---------------- fused weight-prep (fp16 hi/lo) + embedding gather (fp16) ----------
__global__ void k_prep_embed(const float* __restrict__ Wc, const float* __restrict__ Wd,
                             const void* xp, const float* __restrict__ Win) {
    if (blockIdx.x < 96) {
        int i = blockIdx.x * 256 + threadIdx.x;
        if (i < 16384) {
            int n = i >> 7;
            int k = i & 127;
            float v = Wc[k * 128 + n];
            __half h = __float2half_rn(v);
            __half l = __float2half_rn(v - __half2float(h));
            g_Wch[n * 128 + k] = h;
            g_Wcl[n * 128 + k] = l;
        } else {
            int j = i - 16384;
            int n = j >> 7;
            int k = j & 127;
            float v = Wd[k * 64 + n];
            __half h = __float2half_rn(v);
            __half l = __float2half_rn(v - __half2float(h));
            g_Wdh[n * 128 + k] = h;
            g_Wdl[n * 128 + k] = l;
        }
    } else {
        int id = (blockIdx.x - 96) * 256 + threadIdx.x;
        if (id < N_NODES * 16) {
            int v = id >> 4;
            int k0 = (id & 15) * 8;
            int row = load_idx(xp, v, g_x64);
            const float* src = Win + (long)row * EMBED + k0;
            __half hv[8];
            #pragma unroll
            for (int q = 0; q < 8; q++) {
                hv[q] = __float2half_rn(src[q]);
            }
            *(uint4*)(g_h + (long)v * EMBED + k0) = *(uint4*)hv;
        }
    }
}

// ---------------- tensor-core GEMM (mma.sync fp16, no spills) ----------
// CTA tile: 128 rows x 64 cols (blockIdx.y = column group). Both Wh and Wl
// staged upfront; A fragments reused across both passes. 32 acc regs/thread.
template <int NCOLTOT>
__device__ __forceinline__ void mma_gemm_body(const __half* __restrict__ Wh,
                                              const __half* __restrict__ Wl,
                                              __half* __restrict__ C) {
    const int PAD = 136;
    extern __shared__ unsigned short sm[];
    unsigned short* As  = sm;                      // [128][PAD]
    unsigned short* Bhs = As + 128 * PAD;          // [64][PAD]
    unsigned short* Bls = Bhs + 64 * PAD;          // [64][PAD]

    int tid = threadIdx.x;
    int wid = tid >> 5;
    int lane = tid & 31;
    int row0 = blockIdx.x * 128;
    int col0 = blockIdx.y * 64;

    // stage A (128 rows x 128 halfs)
    for (int i = tid; i < 2048; i += 256) {
        int r = i >> 4;
        int k0 = (i & 15) * 8;
        int gr = row0 + r;
        uint4 va = make_uint4(0u, 0u, 0u, 0u);
        if (gr < N_NODES) {
            va = *(const uint4*)(g_h + (long)gr * EMBED + k0);
        }
        *(uint4*)(As + r * PAD + k0) = va;
    }
    // stage Bh and Bl (64 rows x 128 halfs each)
    for (int i = tid; i < 1024; i += 256) {
        int r = i >> 4;
        int k0 = (i & 15) * 8;
        const unsigned short* wh = (const unsigned short*)Wh + (long)(col0 + r) * 128 + k0;
        const unsigned short* wl = (const unsigned short*)Wl + (long)(col0 + r) * 128 + k0;
        *(uint4*)(Bhs + r * PAD + k0) = *(const uint4*)wh;
        *(uint4*)(Bls + r * PAD + k0) = *(const uint4*)wl;
    }
    __syncthreads();

    int m0 = wid * 16;
    float acc[8][4];
    #pragma unroll
    for (int j = 0; j < 8; j++) {
        #pragma unroll
        for (int q = 0; q < 4; q++) acc[j][q] = 0.0f;
    }

    const unsigned int sb = smem_u32(sm);
    // A x4: lanes 0-15 rows m0..m0+15 (k0 half), lanes 16-31 same rows k8 half
    unsigned int a_off = (unsigned int)((m0 + (lane & 15)) * PAD + (lane >> 4) * 8) * 2u;
    // B x4 (two n-tiles): lanes 0-7 tile j rows, lanes 8-15 k8-half,
    //                     lanes 16-23 tile j+1 rows, lanes 24-31 its k8-half
    unsigned int b4_off = (unsigned int)(((lane & 7) + ((lane >> 4) * 8)) * PAD +
                                         (((lane >> 3) & 1) * 8)) * 2u;
    unsigned int a_b = sb + a_off;
    unsigned int bh_b = sb + (unsigned int)(128 * PAD * 2) + b4_off;
    unsigned int bl_b = bh_b + (unsigned int)(64 * PAD * 2);

    #pragma unroll
    for (int ks = 0; ks < 8; ks++) {
        unsigned int h0, h1, h2, h3;
        ldsm_x4(h0, h1, h2, h3, a_b + (unsigned int)(ks * 32));
        #pragma unroll
        for (int j = 0; j < 8; j += 2) {
            unsigned int p0, p1, p2, p3;
            unsigned int q0, q1, q2, q3;
            ldsm_x4(p0, p1, p2, p3, bh_b + (unsigned int)(j * 8 * PAD * 2 + ks * 32));
            ldsm_x4(q0, q1, q2, q3, bl_b + (unsigned int)(j * 8 * PAD * 2 + ks * 32));
            mma_fp16(acc[j],     h0, h1, h2, h3, p0, p1);
            mma_fp16(acc[j + 1], h0, h1, h2, h3, p2, p3);
            mma_fp16(acc[j],     h0, h1, h2, h3, q0, q1);
            mma_fp16(acc[j + 1], h0, h1, h2, h3, q2, q3);
        }
    }

    // epilogue: fp16 stores
    int mrow = m0 + (lane >> 2);
    int nc0 = (lane & 3) * 2;
    int gr0 = row0 + mrow;
    int gr1 = gr0 + 8;
    #pragma unroll
    for (int j = 0; j < 8; j++) {
        int gc = col0 + j * 8 + nc0;
        if (gr0 < N_NODES) {
            *(__half2*)(C + (long)gr0 * NCOLTOT + gc) =
                __floats2half2_rn(acc[j][0], acc[j][1]);
        }
        if (gr1 < N_NODES) {
            *(__half2*)(C + (long)gr1 * NCOLTOT + gc) =
                __floats2half2_rn(acc[j][2], acc[j][3]);
        }
    }
}

__global__ void __launch_bounds__(256, 3) k_mm_conv() {
    mma_gemm_body<128>(g_Wch, g_Wcl, g_t);
}
__global__ void __launch_bounds__(256, 3) k_mm_dec() {
    mma_gemm_body<64>(g_Wdh, g_Wdl, g_t);
}

// ---------------- aggregation (fp16 gathers, fp32 accumulate, unroll 2) ----
__global__ void __launch_bounds__(256) k_agg_conv(const float* __restrict__ bias) {
    const __half* T = g_t;
    int v = blockIdx.x * 8 + (threadIdx.x >> 5);
    int lane = threadIdx.x & 31;
    int lo4 = lane * 4;

    float acc[4];
    float sw = g_selfw[v];
    {
        uint2 raw = *(const uint2*)(T + (long)v * 128 + lo4);
        float2 p0 = __half22float2(*(__half2*)&raw.x);
        float2 p1 = __half22float2(*(__half2*)&raw.y);
        acc[0] = sw * p0.x; acc[1] = sw * p0.y;
        acc[2] = sw * p1.x; acc[3] = sw * p1.y;
    }

    int jb = g_rowptr[v];
    int je = g_rowptr[v + 1];
    int j = jb;
    for (; j + 1 < je; j += 2) {
        int2 e0 = g_edges[j];
        int2 e1 = g_edges[j + 1];
        uint2 r0 = *(const uint2*)(T + (long)e0.x * 128 + lo4);
        uint2 r1 = *(const uint2*)(T + (long)e1.x * 128 + lo4);
        float w0 = __int_as_float(e0.y);
        float w1 = __int_as_float(e1.y);
        float2 a0 = __half22float2(*(__half2*)&r0.x);
        float2 a1 = __half22float2(*(__half2*)&r0.y);
        float2 b0 = __half22float2(*(__half2*)&r1.x);
        float2 b1 = __half22float2(*(__half2*)&r1.y);
        acc[0] = fmaf(w0, a0.x, acc[0]); acc[1] = fmaf(w0, a0.y, acc[1]);
        acc[2] = fmaf(w0, a1.x, acc[2]); acc[3] = fmaf(w0, a1.y, acc[3]);
        acc[0] = fmaf(w1, b0.x, acc[0]); acc[1] = fmaf(w1, b0.y, acc[1]);
        acc[2] = fmaf(w1, b1.x, acc[2]); acc[3] = fmaf(w1, b1.y, acc[3]);
    }
    if (j < je) {
        int2 e0 = g_edges[j];
        uint2 r0 = *(const uint2*)(T + (long)e0.x * 128 + lo4);
        float w0 = __int_as_float(e0.y);
        float2 a0 = __half22float2(*(__half2*)&r0.x);
        float2 a1 = __half22float2(*(__half2*)&r0.y);
        acc[0] = fmaf(w0, a0.x, acc[0]); acc[1] = fmaf(w0, a0.y, acc[1]);
        acc[2] = fmaf(w0, a1.x, acc[2]); acc[3] = fmaf(w0, a1.y, acc[3]);
    }

    __half hv[4];
    #pragma unroll
    for (int i = 0; i < 4; i++) {
        float a = fmaxf(acc[i] + bias[lo4 + i], 0.0f);
        hv[i] = __float2half_rn(a);
    }
    *(uint2*)(g_h + (long)v * 128 + lo4) = *(uint2*)hv;
}

__global__ void __launch_bounds__(256) k_agg_dec(const float* __restrict__ bias,
                                                 float* __restrict__ out) {
    const __half* T = g_t;
    int v = blockIdx.x * 8 + (threadIdx.x >> 5);
    int lane = threadIdx.x & 31;
    int lo2 = lane * 2;

    float acc[2];
    float sw = g_selfw[v];
    {
        unsigned int raw = *(const unsigned int*)(T + (long)v * 64 + lo2);
        float2 p0 = __half22float2(*(__half2*)&raw);
        acc[0] = sw * p0.x; acc[1] = sw * p0.y;
    }

    int jb = g_rowptr[v];
    int je = g_rowptr[v + 1];
    int j = jb;
    for (; j + 1 < je; j += 2) {
        int2 e0 = g_edges[j];
        int2 e1 = g_edges[j + 1];
        unsigned int r0 = *(const unsigned int*)(T + (long)e0.x * 64 + lo2);
        unsigned int r1 = *(const unsigned int*)(T + (long)e1.x * 64 + lo2);
        float w0 = __int_as_float(e0.y);
        float w1 = __int_as_float(e1.y);
        float2 a0 = __half22float2(*(__half2*)&r0);
        float2 b0 = __half22float2(*(__half2*)&r1);
        acc[0] = fmaf(w0, a0.x, acc[0]); acc[1] = fmaf(w0, a0.y, acc[1]);
        acc[0] = fmaf(w1, b0.x, acc[0]); acc[1] = fmaf(w1, b0.y, acc[1]);
    }
    if (j < je) {
        int2 e0 = g_edges[j];
        unsigned int r0 = *(const unsigned int*)(T + (long)e0.x * 64 + lo2);
        float w0 = __int_as_float(e0.y);
        float2 a0 = __half22float2(*(__half2*)&r0);
        acc[0] = fmaf(w0, a0.x, acc[0]); acc[1] = fmaf(w0, a0.y, acc[1]);
    }

    float2 o;
    o.x = acc[0] + bias[lo2];
    o.y = acc[1] + bias[lo2 + 1];
    *(float2*)(out + (long)v * 64 + lo2) = o;
}

// ---------------- launch ----------------
// Order keeps k_mm_conv as the 4th launch (ncu capture slot); deps intact:
// prep_embed needs init; mm_conv needs prep_embed; agg needs scan_dinv+fill.
extern "C" void kernel_launch(void* const* d_in, const int* in_sizes, int n_in,
                              void* d_out, int out_size) {
    const void*  x      = d_in[0];
    const void*  ei     = d_in[1];
    const float* W_in   = (const float*)d_in[2];
    const float* W_conv = (const float*)d_in[3];
    const float* b_conv = (const float*)d_in[4];
    const float* W_dec  = (const float*)d_in[5];
    const float* b_dec  = (const float*)d_in[6];
    float* out = (float*)d_out;

    const int PAD = 136;
    const int SMEM_GEMM = (128 + 64 + 64) * PAD * 2;  // 69632
    cudaFuncSetAttribute(k_mm_conv, cudaFuncAttributeMaxDynamicSharedMemorySize, SMEM_GEMM);
    cudaFuncSetAttribute(k_mm_dec,  cudaFuncAttributeMaxDynamicSharedMemorySize, SMEM_GEMM);

    const int GEMM_BLOCKS = (N_NODES + 127) / 128;   // 313
    dim3 grid_conv(GEMM_BLOCKS, 2);
    dim3 grid_dec(GEMM_BLOCKS, 1);

    k_init<<<(N_NODES + 255) / 256, 256>>>(x, ei);                                 // 1
    k_count<<<(N_EDGES + 255) / 256, 256>>>(ei);                                   // 2
    k_prep_embed<<<96 + (N_NODES * 16 + 255) / 256, 256>>>(W_conv, W_dec, x, W_in);// 3
    k_mm_conv<<<grid_conv, 256, SMEM_GEMM>>>();                                    // 4 (ncu)
    k_scan_dinv<<<1, 1024>>>();                                                    // 5
    k_fill<<<(N_EDGES + 255) / 256, 256>>>(ei);                                    // 6
    k_agg_conv<<<5000, 256>>>(b_conv);                                             // 7

    for (int it = 0; it < 3; it++) {
        k_mm_conv<<<grid_conv, 256, SMEM_GEMM>>>();
        k_agg_conv<<<5000, 256>>>(b_conv);
    }
    k_mm_dec<<<grid_dec, 256, SMEM_GEMM>>>();
    k_agg_dec<<<5000, 256>>>(b_dec, out);
}